// round 9
// baseline (speedup 1.0000x reference)
#include <cuda_runtime.h>
#include <cuda_bf16.h>
#include <cstdint>

#define B_   2
#define LQ_  4096
#define C_   384
#define M_   4
#define H_   6
#define P_   4
#define DH_  64
#define ROWS_ (B_ * LQ_)          // 8192
#define OFFN_ 48
#define AWN_  24
#define FUSEN_ (M_ * (OFFN_ + AWN_))   // 288
#define KOUT_ (M_ * C_)                // 1536

// ---------------- scratch ----------------------------------------------------
__device__ __nv_bfloat16 g_qn    [ROWS_ * C_];
__device__ __nv_bfloat16 g_fn    [M_ * ROWS_ * C_];
__device__ __nv_bfloat16 g_value [M_ * ROWS_ * C_];
__device__ float         g_offaw [ROWS_ * FUSEN_];
__device__ __nv_bfloat16 g_attn  [ROWS_ * KOUT_];
__device__ __nv_bfloat16 g_Wv_b  [M_ * C_ * C_];
__device__ __nv_bfloat16 g_Wfo_b [C_ * FUSEN_];
__device__ float         g_bfo   [FUSEN_];
__device__ __nv_bfloat16 g_Wout_b[KOUT_ * C_];
__device__ float         g_bout  [C_];

// ---------------- fused weight packing (single launch) -----------------------
#define S1_ (M_ * C_ * C_)
#define S2_ (C_ * FUSEN_)
#define S3_ (M_ * C_ * C_)
__global__ void pack_all_kernel(const float* __restrict__ Wv,
                                const float* __restrict__ Woff,
                                const float* __restrict__ Waw,
                                const float* __restrict__ Wout,
                                const float* __restrict__ gamma,
                                const float* __restrict__ boff,
                                const float* __restrict__ baw,
                                const float* __restrict__ bout,
                                __nv_bfloat16* __restrict__ Wv_b,
                                __nv_bfloat16* __restrict__ Wfo_b,
                                __nv_bfloat16* __restrict__ Wout_b,
                                float* __restrict__ bfo,
                                float* __restrict__ bout_t)
{
    int i = blockIdx.x * blockDim.x + threadIdx.x;
    if (i < S1_) {
        Wv_b[i] = __float2bfloat16(Wv[i]);
    } else if (i < S1_ + S2_) {
        int j = i - S1_;
        int k = j / FUSEN_, jj = j % FUSEN_;
        int m = jj / 72, r = jj % 72;
        float v = (r < OFFN_) ? Woff[((size_t)m * C_ + k) * OFFN_ + r]
                              : Waw [((size_t)m * C_ + k) * AWN_  + (r - OFFN_)];
        Wfo_b[j] = __float2bfloat16(v);
    } else if (i < S1_ + S2_ + S3_) {
        int j = i - S1_ - S2_;
        int m = j / (C_ * C_);
        int c = j % C_;
        Wout_b[j] = __float2bfloat16(gamma[m * C_ + c] * Wout[j]);
    } else {
        int j = i - S1_ - S2_ - S3_;
        if (j < FUSEN_) {
            int m = j / 72, r = j % 72;
            bfo[j] = (r < OFFN_) ? boff[m * OFFN_ + r] : baw[m * AWN_ + r - OFFN_];
        } else if (j < FUSEN_ + C_) {
            int c = j - FUSEN_;
            float s = 0.f;
            #pragma unroll
            for (int m = 0; m < M_; m++) s += gamma[m * C_ + c] * bout[m * C_ + c];
            bout_t[c] = s;
        }
    }
}
#define PACK_TOTAL_ (S1_ + S2_ + S3_ + FUSEN_ + C_)

// ---------------- warp-per-row LayerNorm (5 sources fused) -------------------
__global__ void ln_kernel(const float* __restrict__ query,
                          const float* __restrict__ feat,
                          const float* __restrict__ feato,
                          const float* __restrict__ qn_g, const float* __restrict__ qn_b,
                          const float* __restrict__ fn_g, const float* __restrict__ fn_b,
                          __nv_bfloat16* __restrict__ qn,
                          __nv_bfloat16* __restrict__ fnAll)
{
    const int grow = blockIdx.x * 8 + (threadIdx.x >> 5);
    const int l = threadIdx.x & 31;
    const int src = grow / ROWS_;
    const int row = grow - src * ROWS_;

    const float* xbase = (src == 0) ? query : (src == 1 ? feat
                         : feato + (size_t)(src - 2) * ROWS_ * C_);
    const float* g = (src == 0) ? qn_g : fn_g + (src - 1) * C_;
    const float* b = (src == 0) ? qn_b : fn_b + (src - 1) * C_;
    __nv_bfloat16* y = (src == 0) ? qn + (size_t)row * C_
                                  : fnAll + ((size_t)(src - 1) * ROWS_ + row) * C_;
    const float4* xr = (const float4*)(xbase + (size_t)row * C_);

    float4 v[3];
    float sum = 0.f, sumsq = 0.f;
    #pragma unroll
    for (int k = 0; k < 3; k++) {
        v[k] = xr[l + 32 * k];
        sum   += v[k].x + v[k].y + v[k].z + v[k].w;
        sumsq += v[k].x * v[k].x + v[k].y * v[k].y + v[k].z * v[k].z + v[k].w * v[k].w;
    }
    #pragma unroll
    for (int o = 16; o; o >>= 1) {
        sum   += __shfl_xor_sync(0xffffffffu, sum, o);
        sumsq += __shfl_xor_sync(0xffffffffu, sumsq, o);
    }
    const float mean = sum * (1.f / C_);
    const float var  = sumsq * (1.f / C_) - mean * mean;
    const float inv  = rsqrtf(var + 1e-6f);

    const float4* g4 = (const float4*)g;
    const float4* b4 = (const float4*)b;
    #pragma unroll
    for (int k = 0; k < 3; k++) {
        float4 gg = g4[l + 32 * k];
        float4 bb = b4[l + 32 * k];
        __nv_bfloat16 o0 = __float2bfloat16((v[k].x - mean) * inv * gg.x + bb.x);
        __nv_bfloat16 o1 = __float2bfloat16((v[k].y - mean) * inv * gg.y + bb.y);
        __nv_bfloat16 o2 = __float2bfloat16((v[k].z - mean) * inv * gg.z + bb.z);
        __nv_bfloat16 o3 = __float2bfloat16((v[k].w - mean) * inv * gg.w + bb.w);
        uint2 pk;
        pk.x = ((uint32_t)__bfloat16_as_ushort(o1) << 16) | __bfloat16_as_ushort(o0);
        pk.y = ((uint32_t)__bfloat16_as_ushort(o3) << 16) | __bfloat16_as_ushort(o2);
        *(uint2*)&y[(l + 32 * k) * 4] = pk;
    }
}

#define AS_STRIDE 40
#define BS_STRIDE 72
#define BS2_STRIDE 136

// ---------------- fused GEMM launch: value (z<4) + offaw (z==4) --------------
// grid (5, 64, 5); value path uses x<3 (128-wide cols), offaw path x<5 (64-wide).
__global__ __launch_bounds__(256, 3) void gemm_fused(
    const __nv_bfloat16* __restrict__ fn,   const __nv_bfloat16* __restrict__ Wv_b,
    const float* __restrict__ bv,           __nv_bfloat16* __restrict__ value,
    const __nv_bfloat16* __restrict__ qn,   const __nv_bfloat16* __restrict__ Wfo_b,
    const float* __restrict__ bfo,          float* __restrict__ offaw)
{
    __shared__ alignas(16) __nv_bfloat16 AsBuf[2][128][AS_STRIDE];
    __shared__ alignas(16) __nv_bfloat16 BsBuf[2][32][BS2_STRIDE];

    if (blockIdx.z < M_ && blockIdx.x >= 3) return;

    const int tid = threadIdx.x;
    const int w = tid >> 5, l = tid & 31;
    const int row0 = blockIdx.y * 128;
    const int KIT = C_ / 32;

    if (blockIdx.z < M_) {
        // ================= value path: 128x128 tile, N=C_=384 =================
        const int zb = blockIdx.z;
        const __nv_bfloat16* A = fn + (size_t)zb * ROWS_ * C_;
        const __nv_bfloat16* W = Wv_b + (size_t)zb * C_ * C_;
        const float* bias = bv + (size_t)zb * C_;
        const int N = C_;
        const int warpM = (w & 1) << 6;
        const int warpN = (w >> 1) << 5;
        const int col0 = blockIdx.x * 128;

        float acc[4][4][4];
        #pragma unroll
        for (int mi = 0; mi < 4; mi++)
            #pragma unroll
            for (int nj = 0; nj < 4; nj++)
                #pragma unroll
                for (int q = 0; q < 4; q++) acc[mi][nj][q] = 0.f;

        for (int it = 0; it <= KIT; it++) {
            if (it < KIT) {
                const int st = it & 1;
                const int k0 = it * 32;
                #pragma unroll
                for (int i = 0; i < 2; i++) {
                    int q = tid * 2 + i;
                    int r = q >> 2, kc = q & 3;
                    uint32_t d = (uint32_t)__cvta_generic_to_shared(&AsBuf[st][r][kc * 8]);
                    const __nv_bfloat16* s = A + (size_t)(row0 + r) * C_ + k0 + kc * 8;
                    asm volatile("cp.async.cg.shared.global [%0], [%1], 16;\n" :: "r"(d), "l"(s));
                }
                #pragma unroll
                for (int i = 0; i < 2; i++) {
                    int r = (tid >> 4) + i * 16;
                    int c = (tid & 15) * 8;
                    uint32_t d = (uint32_t)__cvta_generic_to_shared(&BsBuf[st][r][c]);
                    const __nv_bfloat16* s = W + (size_t)(k0 + r) * N + col0 + c;
                    asm volatile("cp.async.cg.shared.global [%0], [%1], 16;\n" :: "r"(d), "l"(s));
                }
                asm volatile("cp.async.commit_group;\n");
            }
            if (it == 0) continue;
            if (it < KIT) asm volatile("cp.async.wait_group 1;\n");
            else          asm volatile("cp.async.wait_group 0;\n");
            __syncthreads();

            const int st = (it - 1) & 1;
            #pragma unroll
            for (int s = 0; s < 2; s++) {
                const int k16 = s * 16;
                uint32_t a[4][4], bfr[2][4];
                #pragma unroll
                for (int mi = 0; mi < 4; mi++) {
                    uint32_t addr = (uint32_t)__cvta_generic_to_shared(
                        &AsBuf[st][warpM + mi * 16 + (l & 15)][k16 + (l >> 4) * 8]);
                    asm volatile("ldmatrix.sync.aligned.m8n8.x4.shared.b16 {%0,%1,%2,%3}, [%4];\n"
                        : "=r"(a[mi][0]), "=r"(a[mi][1]), "=r"(a[mi][2]), "=r"(a[mi][3]) : "r"(addr));
                }
                #pragma unroll
                for (int np = 0; np < 2; np++) {
                    uint32_t addr = (uint32_t)__cvta_generic_to_shared(
                        &BsBuf[st][k16 + (l & 15)][warpN + np * 16 + (l >> 4) * 8]);
                    asm volatile("ldmatrix.sync.aligned.m8n8.x4.trans.shared.b16 {%0,%1,%2,%3}, [%4];\n"
                        : "=r"(bfr[np][0]), "=r"(bfr[np][1]), "=r"(bfr[np][2]), "=r"(bfr[np][3]) : "r"(addr));
                }
                #pragma unroll
                for (int mi = 0; mi < 4; mi++)
                    #pragma unroll
                    for (int nj = 0; nj < 4; nj++) {
                        uint32_t b0 = bfr[nj >> 1][(nj & 1) * 2];
                        uint32_t b1 = bfr[nj >> 1][(nj & 1) * 2 + 1];
                        asm volatile(
                            "mma.sync.aligned.m16n8k16.row.col.f32.bf16.bf16.f32 "
                            "{%0,%1,%2,%3}, {%4,%5,%6,%7}, {%8,%9}, {%0,%1,%2,%3};\n"
                            : "+f"(acc[mi][nj][0]), "+f"(acc[mi][nj][1]),
                              "+f"(acc[mi][nj][2]), "+f"(acc[mi][nj][3])
                            : "r"(a[mi][0]), "r"(a[mi][1]), "r"(a[mi][2]), "r"(a[mi][3]),
                              "r"(b0), "r"(b1));
                    }
            }
            __syncthreads();
        }

        __nv_bfloat16* Cm = value + (size_t)zb * ROWS_ * N;
        #pragma unroll
        for (int mi = 0; mi < 4; mi++) {
            const int r = row0 + warpM + mi * 16 + (l >> 2);
            #pragma unroll
            for (int nj = 0; nj < 4; nj++) {
                const int c = col0 + warpN + nj * 8 + ((l & 3) << 1);
                const float b0 = bias[c], b1 = bias[c + 1];
                const size_t o0 = (size_t)r * N + c;
                const size_t o1 = (size_t)(r + 8) * N + c;
                *(__nv_bfloat162*)&Cm[o0] = __nv_bfloat162(
                    __float2bfloat16(acc[mi][nj][0] + b0), __float2bfloat16(acc[mi][nj][1] + b1));
                *(__nv_bfloat162*)&Cm[o1] = __nv_bfloat162(
                    __float2bfloat16(acc[mi][nj][2] + b0), __float2bfloat16(acc[mi][nj][3] + b1));
            }
        }
    } else {
        // ================= offaw path: 128x64 tile, N=288 =====================
        const int N = FUSEN_;
        const int warpM = (w & 3) << 5;
        const int warpN = (w >> 2) << 5;
        const int col0 = blockIdx.x * 64;
        __nv_bfloat16 (*Bs)[BS_STRIDE] = (__nv_bfloat16 (*)[BS_STRIDE])&BsBuf[0][0][0];

        float acc[2][4][4];
        #pragma unroll
        for (int mi = 0; mi < 2; mi++)
            #pragma unroll
            for (int nj = 0; nj < 4; nj++)
                #pragma unroll
                for (int q = 0; q < 4; q++) acc[mi][nj][q] = 0.f;

        const int br = tid >> 3, bch = tid & 7;

        for (int it = 0; it <= KIT; it++) {
            if (it < KIT) {
                const int st = it & 1;
                const int k0 = it * 32;
                #pragma unroll
                for (int i = 0; i < 2; i++) {
                    int q = tid * 2 + i;
                    int r = q >> 2, kc = q & 3;
                    uint32_t d = (uint32_t)__cvta_generic_to_shared(&AsBuf[st][r][kc * 8]);
                    const __nv_bfloat16* s = qn + (size_t)(row0 + r) * C_ + k0 + kc * 8;
                    asm volatile("cp.async.cg.shared.global [%0], [%1], 16;\n" :: "r"(d), "l"(s));
                }
                {
                    int c = bch * 8;
                    uint32_t d = (uint32_t)__cvta_generic_to_shared(&Bs[st * 32 + br][c]);
                    const __nv_bfloat16* s = Wfo_b + (size_t)(k0 + br) * N + col0 + c;
                    int sb = (col0 + c < N) ? 16 : 0;
                    if (sb == 0) s = Wfo_b;
                    asm volatile("cp.async.cg.shared.global [%0], [%1], 16, %2;\n"
                                 :: "r"(d), "l"(s), "r"(sb));
                }
                asm volatile("cp.async.commit_group;\n");
            }
            if (it == 0) continue;
            if (it < KIT) asm volatile("cp.async.wait_group 1;\n");
            else          asm volatile("cp.async.wait_group 0;\n");
            __syncthreads();

            const int st = (it - 1) & 1;
            #pragma unroll
            for (int s = 0; s < 2; s++) {
                const int k16 = s * 16;
                uint32_t a[2][4], bfr[2][4];
                #pragma unroll
                for (int mi = 0; mi < 2; mi++) {
                    uint32_t addr = (uint32_t)__cvta_generic_to_shared(
                        &AsBuf[st][warpM + mi * 16 + (l & 15)][k16 + (l >> 4) * 8]);
                    asm volatile("ldmatrix.sync.aligned.m8n8.x4.shared.b16 {%0,%1,%2,%3}, [%4];\n"
                        : "=r"(a[mi][0]), "=r"(a[mi][1]), "=r"(a[mi][2]), "=r"(a[mi][3]) : "r"(addr));
                }
                #pragma unroll
                for (int np = 0; np < 2; np++) {
                    uint32_t addr = (uint32_t)__cvta_generic_to_shared(
                        &Bs[st * 32 + k16 + (l & 15)][warpN + np * 16 + (l >> 4) * 8]);
                    asm volatile("ldmatrix.sync.aligned.m8n8.x4.trans.shared.b16 {%0,%1,%2,%3}, [%4];\n"
                        : "=r"(bfr[np][0]), "=r"(bfr[np][1]), "=r"(bfr[np][2]), "=r"(bfr[np][3]) : "r"(addr));
                }
                #pragma unroll
                for (int mi = 0; mi < 2; mi++)
                    #pragma unroll
                    for (int nj = 0; nj < 4; nj++) {
                        uint32_t b0 = bfr[nj >> 1][(nj & 1) * 2];
                        uint32_t b1 = bfr[nj >> 1][(nj & 1) * 2 + 1];
                        asm volatile(
                            "mma.sync.aligned.m16n8k16.row.col.f32.bf16.bf16.f32 "
                            "{%0,%1,%2,%3}, {%4,%5,%6,%7}, {%8,%9}, {%0,%1,%2,%3};\n"
                            : "+f"(acc[mi][nj][0]), "+f"(acc[mi][nj][1]),
                              "+f"(acc[mi][nj][2]), "+f"(acc[mi][nj][3])
                            : "r"(a[mi][0]), "r"(a[mi][1]), "r"(a[mi][2]), "r"(a[mi][3]),
                              "r"(b0), "r"(b1));
                    }
            }
            __syncthreads();
        }

        #pragma unroll
        for (int mi = 0; mi < 2; mi++) {
            const int r = row0 + warpM + mi * 16 + (l >> 2);
            #pragma unroll
            for (int nj = 0; nj < 4; nj++) {
                const int c = col0 + warpN + nj * 8 + ((l & 3) << 1);
                if (c >= N) continue;
                const float b0 = bfo[c], b1 = bfo[c + 1];
                *(float2*)&offaw[(size_t)r * N + c] =
                    make_float2(acc[mi][nj][0] + b0, acc[mi][nj][1] + b1);
                *(float2*)&offaw[(size_t)(r + 8) * N + c] =
                    make_float2(acc[mi][nj][2] + b0, acc[mi][nj][3] + b1);
            }
        }
    }
}

// ---------------- final GEMM: out = query + attn @ Wout' + bout' -------------
__global__ __launch_bounds__(256, 3) void gemm_final(
    const __nv_bfloat16* __restrict__ A,
    const __nv_bfloat16* __restrict__ W,
    const float* __restrict__ bias,
    float* __restrict__ Cm,
    const float* __restrict__ residual)
{
    __shared__ alignas(16) __nv_bfloat16 As[2][128][AS_STRIDE];
    __shared__ alignas(16) __nv_bfloat16 Bs[2][32][BS2_STRIDE];
    const int N = C_;
    const int KA = KOUT_;
    const int tid = threadIdx.x;
    const int w = tid >> 5, l = tid & 31;
    const int warpM = (w & 1) << 6;
    const int warpN = (w >> 1) << 5;
    const int row0 = blockIdx.y * 128;
    const int col0 = blockIdx.x * 128;

    float acc[4][4][4];
    #pragma unroll
    for (int mi = 0; mi < 4; mi++)
        #pragma unroll
        for (int nj = 0; nj < 4; nj++)
            #pragma unroll
            for (int q = 0; q < 4; q++) acc[mi][nj][q] = 0.f;

    const int KIT = KA / 32;

    for (int it = 0; it <= KIT; it++) {
        if (it < KIT) {
            const int st = it & 1;
            const int k0 = it * 32;
            #pragma unroll
            for (int i = 0; i < 2; i++) {
                int q = tid * 2 + i;
                int r = q >> 2, kc = q & 3;
                uint32_t d = (uint32_t)__cvta_generic_to_shared(&As[st][r][kc * 8]);
                const __nv_bfloat16* s = A + (size_t)(row0 + r) * KA + k0 + kc * 8;
                asm volatile("cp.async.cg.shared.global [%0], [%1], 16;\n" :: "r"(d), "l"(s));
            }
            #pragma unroll
            for (int i = 0; i < 2; i++) {
                int r = (tid >> 4) + i * 16;
                int c = (tid & 15) * 8;
                uint32_t d = (uint32_t)__cvta_generic_to_shared(&Bs[st][r][c]);
                const __nv_bfloat16* s = W + (size_t)(k0 + r) * N + col0 + c;
                asm volatile("cp.async.cg.shared.global [%0], [%1], 16;\n" :: "r"(d), "l"(s));
            }
            asm volatile("cp.async.commit_group;\n");
        }
        if (it == 0) continue;
        if (it < KIT) asm volatile("cp.async.wait_group 1;\n");
        else          asm volatile("cp.async.wait_group 0;\n");
        __syncthreads();

        const int st = (it - 1) & 1;
        #pragma unroll
        for (int s = 0; s < 2; s++) {
            const int k16 = s * 16;
            uint32_t a[4][4], bfr[2][4];
            #pragma unroll
            for (int mi = 0; mi < 4; mi++) {
                uint32_t addr = (uint32_t)__cvta_generic_to_shared(
                    &As[st][warpM + mi * 16 + (l & 15)][k16 + (l >> 4) * 8]);
                asm volatile("ldmatrix.sync.aligned.m8n8.x4.shared.b16 {%0,%1,%2,%3}, [%4];\n"
                    : "=r"(a[mi][0]), "=r"(a[mi][1]), "=r"(a[mi][2]), "=r"(a[mi][3]) : "r"(addr));
            }
            #pragma unroll
            for (int np = 0; np < 2; np++) {
                uint32_t addr = (uint32_t)__cvta_generic_to_shared(
                    &Bs[st][k16 + (l & 15)][warpN + np * 16 + (l >> 4) * 8]);
                asm volatile("ldmatrix.sync.aligned.m8n8.x4.trans.shared.b16 {%0,%1,%2,%3}, [%4];\n"
                    : "=r"(bfr[np][0]), "=r"(bfr[np][1]), "=r"(bfr[np][2]), "=r"(bfr[np][3]) : "r"(addr));
            }
            #pragma unroll
            for (int mi = 0; mi < 4; mi++)
                #pragma unroll
                for (int nj = 0; nj < 4; nj++) {
                    uint32_t b0 = bfr[nj >> 1][(nj & 1) * 2];
                    uint32_t b1 = bfr[nj >> 1][(nj & 1) * 2 + 1];
                    asm volatile(
                        "mma.sync.aligned.m16n8k16.row.col.f32.bf16.bf16.f32 "
                        "{%0,%1,%2,%3}, {%4,%5,%6,%7}, {%8,%9}, {%0,%1,%2,%3};\n"
                        : "+f"(acc[mi][nj][0]), "+f"(acc[mi][nj][1]),
                          "+f"(acc[mi][nj][2]), "+f"(acc[mi][nj][3])
                        : "r"(a[mi][0]), "r"(a[mi][1]), "r"(a[mi][2]), "r"(a[mi][3]),
                          "r"(b0), "r"(b1));
                }
        }
        __syncthreads();
    }

    #pragma unroll
    for (int mi = 0; mi < 4; mi++) {
        const int r = row0 + warpM + mi * 16 + (l >> 2);
        #pragma unroll
        for (int nj = 0; nj < 4; nj++) {
            const int c = col0 + warpN + nj * 8 + ((l & 3) << 1);
            const float b0 = bias[c], b1 = bias[c + 1];
            const size_t o0 = (size_t)r * N + c;
            const size_t o1 = (size_t)(r + 8) * N + c;
            float2 r0 = *(const float2*)&residual[o0];
            float2 r1 = *(const float2*)&residual[o1];
            *(float2*)&Cm[o0] = make_float2(r0.x + acc[mi][nj][0] + b0, r0.y + acc[mi][nj][1] + b1);
            *(float2*)&Cm[o1] = make_float2(r1.x + acc[mi][nj][2] + b0, r1.y + acc[mi][nj][3] + b1);
        }
    }
}

// ---------------- batched sampler: 8 channels/thread via uint4 ---------------
__global__ void sample_kernel(const __nv_bfloat16* __restrict__ valueAll,
                              const float* __restrict__ ref,
                              const float* __restrict__ offaw,
                              __nv_bfloat16* __restrict__ attn,
                              const int* __restrict__ shapes_raw,
                              const int* __restrict__ lstart_raw)
{
    const int t   = threadIdx.x;
    const int idx = blockIdx.x * 32 + (t >> 3);
    const int l8  = t & 7;
    const int m   = idx / (ROWS_ * H_);
    const int rem = idx % (ROWS_ * H_);
    const int h   = rem % H_;
    const int bq  = rem / H_;
    const int b   = bq / LQ_;

    const int gh = shapes_raw[0];
    const int w1 = shapes_raw[1];
    const int gw = (w1 != 0) ? w1 : shapes_raw[2];
    const int st = lstart_raw[0];

    const float* fo = offaw + (size_t)bq * FUSEN_ + m * 72;

    float a4[P_];
    float amax = -1e30f;
    #pragma unroll
    for (int p = 0; p < P_; p++) {
        a4[p] = fo[OFFN_ + h * P_ + p];
        amax = fmaxf(amax, a4[p]);
    }
    float asum = 0.f;
    #pragma unroll
    for (int p = 0; p < P_; p++) { a4[p] = __expf(a4[p] - amax); asum += a4[p]; }
    const float ainv = 1.f / asum;

    const float rx = ref[(size_t)bq * 2 + 0];
    const float ry = ref[(size_t)bq * 2 + 1];
    const float inv_w = 1.f / (float)gw;
    const float inv_h = 1.f / (float)gh;

    const uint4* vb = (const uint4*)(valueAll + (size_t)m * ROWS_ * C_);
    const size_t hbase = ((size_t)b * LQ_) * H_ + h;

    float out[8] = {};
    #pragma unroll
    for (int p = 0; p < P_; p++) {
        const float ox = fo[h * (P_ * 2) + p * 2 + 0];
        const float oy = fo[h * (P_ * 2) + p * 2 + 1];
        const float x = (rx + ox * inv_w) * (float)gw - 0.5f;
        const float y = (ry + oy * inv_h) * (float)gh - 0.5f;
        const float xf = floorf(x);
        const float yf = floorf(y);
        const int x0 = (int)xf;
        const int y0 = (int)yf;
        const float wx = x - xf;
        const float wy = y - yf;
        const float aws = a4[p] * ainv;

        #pragma unroll
        for (int cy = 0; cy < 2; cy++) {
            const int yi = y0 + cy;
            if (yi < 0 || yi >= gh) continue;
            const float wyc = (cy ? wy : (1.f - wy)) * aws;
            #pragma unroll
            for (int cx = 0; cx < 2; cx++) {
                const int xi = x0 + cx;
                if (xi < 0 || xi >= gw) continue;
                const float wgt = wyc * (cx ? wx : (1.f - wx));
                const int pos = st + yi * gw + xi;
                uint4 v = vb[(hbase + (size_t)pos * H_) * 8 + l8];
                const uint32_t* vw = (const uint32_t*)&v;
                #pragma unroll
                for (int k = 0; k < 4; k++) {
                    __nv_bfloat162 pr = *(const __nv_bfloat162*)&vw[k];
                    out[2 * k]     = fmaf(wgt, __bfloat162float(pr.x), out[2 * k]);
                    out[2 * k + 1] = fmaf(wgt, __bfloat162float(pr.y), out[2 * k + 1]);
                }
            }
        }
    }
    uint4 pk;
    uint32_t* pw = (uint32_t*)&pk;
    #pragma unroll
    for (int k = 0; k < 4; k++) {
        __nv_bfloat162 pr(__float2bfloat16(out[2 * k]), __float2bfloat16(out[2 * k + 1]));
        pw[k] = *(const uint32_t*)&pr;
    }
    *(uint4*)(attn + (size_t)bq * KOUT_ + m * C_ + h * DH_ + l8 * 8) = pk;
}

// ---------------- driver -----------------------------------------------------
extern "C" void kernel_launch(void* const* d_in, const int* in_sizes, int n_in,
                              void* d_out, int out_size)
{
    const float* query = (const float*)d_in[0];
    const float* ref   = (const float*)d_in[1];
    const float* feat  = (const float*)d_in[2];
    const float* feato = (const float*)d_in[3];
    const float* qn_g  = (const float*)d_in[4];
    const float* qn_b  = (const float*)d_in[5];
    const float* fn_g  = (const float*)d_in[6];
    const float* fn_b  = (const float*)d_in[7];
    const float* Wv    = (const float*)d_in[8];
    const float* bv    = (const float*)d_in[9];
    const float* Woff  = (const float*)d_in[10];
    const float* boff  = (const float*)d_in[11];
    const float* Waw   = (const float*)d_in[12];
    const float* baw   = (const float*)d_in[13];
    const float* Wout  = (const float*)d_in[14];
    const float* bout  = (const float*)d_in[15];
    const float* gamma = (const float*)d_in[16];
    const int* shapes  = (const int*)d_in[17];
    const int* lstart  = (const int*)d_in[18];
    float* out = (float*)d_out;

    __nv_bfloat16 *qn, *fn, *value, *attn, *Wv_b, *Wfo_b, *Wout_b;
    float *offaw, *bfo, *bout_t;
    cudaGetSymbolAddress((void**)&qn,     g_qn);
    cudaGetSymbolAddress((void**)&fn,     g_fn);
    cudaGetSymbolAddress((void**)&value,  g_value);
    cudaGetSymbolAddress((void**)&offaw,  g_offaw);
    cudaGetSymbolAddress((void**)&attn,   g_attn);
    cudaGetSymbolAddress((void**)&Wv_b,   g_Wv_b);
    cudaGetSymbolAddress((void**)&Wfo_b,  g_Wfo_b);
    cudaGetSymbolAddress((void**)&bfo,    g_bfo);
    cudaGetSymbolAddress((void**)&Wout_b, g_Wout_b);
    cudaGetSymbolAddress((void**)&bout_t, g_bout);

    pack_all_kernel<<<(PACK_TOTAL_ + 255) / 256, 256>>>(
        Wv, Woff, Waw, Wout, gamma, boff, baw, bout,
        Wv_b, Wfo_b, Wout_b, bfo, bout_t);

    ln_kernel<<<5 * ROWS_ / 8, 256>>>(query, feat, feato, qn_g, qn_b, fn_g, fn_b, qn, fn);

    gemm_fused<<<dim3(5, ROWS_ / 128, M_ + 1), 256>>>(
        fn, Wv_b, bv, value, qn, Wfo_b, bfo, offaw);

    sample_kernel<<<(M_ * ROWS_ * H_) / 32, 256>>>(value, ref, offaw, attn, shapes, lstart);

    gemm_final<<<dim3(C_ / 128, ROWS_ / 128), 256>>>(attn, Wout_b, bout_t, out, query);
}

// round 10
// speedup vs baseline: 1.0497x; 1.0497x over previous
#include <cuda_runtime.h>
#include <cuda_bf16.h>
#include <cstdint>

#define B_   2
#define LQ_  4096
#define C_   384
#define M_   4
#define H_   6
#define P_   4
#define DH_  64
#define ROWS_ (B_ * LQ_)          // 8192
#define OFFN_ 48
#define AWN_  24
#define FUSEN_ (M_ * (OFFN_ + AWN_))   // 288
#define KOUT_ (M_ * C_)                // 1536

// ---------------- scratch ----------------------------------------------------
__device__ __nv_bfloat16 g_qn    [ROWS_ * C_];
__device__ __nv_bfloat16 g_fn    [M_ * ROWS_ * C_];
__device__ __nv_bfloat16 g_value [M_ * ROWS_ * C_];
__device__ float         g_offaw [ROWS_ * FUSEN_];
__device__ __nv_bfloat16 g_attn  [ROWS_ * KOUT_];
__device__ __nv_bfloat16 g_Wv_b  [M_ * C_ * C_];
__device__ __nv_bfloat16 g_Wfo_b [C_ * FUSEN_];
__device__ float         g_bfo   [FUSEN_];
__device__ __nv_bfloat16 g_Wout_b[KOUT_ * C_];
__device__ float         g_bout  [C_];

// ---------------- fused weight packing (single launch) -----------------------
#define S1_ (M_ * C_ * C_)
#define S2_ (C_ * FUSEN_)
#define S3_ (M_ * C_ * C_)
__global__ void pack_all_kernel(const float* __restrict__ Wv,
                                const float* __restrict__ Woff,
                                const float* __restrict__ Waw,
                                const float* __restrict__ Wout,
                                const float* __restrict__ gamma,
                                const float* __restrict__ boff,
                                const float* __restrict__ baw,
                                const float* __restrict__ bout,
                                __nv_bfloat16* __restrict__ Wv_b,
                                __nv_bfloat16* __restrict__ Wfo_b,
                                __nv_bfloat16* __restrict__ Wout_b,
                                float* __restrict__ bfo,
                                float* __restrict__ bout_t)
{
    int i = blockIdx.x * blockDim.x + threadIdx.x;
    if (i < S1_) {
        Wv_b[i] = __float2bfloat16(Wv[i]);
    } else if (i < S1_ + S2_) {
        int j = i - S1_;
        int k = j / FUSEN_, jj = j % FUSEN_;
        int m = jj / 72, r = jj % 72;
        float v = (r < OFFN_) ? Woff[((size_t)m * C_ + k) * OFFN_ + r]
                              : Waw [((size_t)m * C_ + k) * AWN_  + (r - OFFN_)];
        Wfo_b[j] = __float2bfloat16(v);
    } else if (i < S1_ + S2_ + S3_) {
        int j = i - S1_ - S2_;
        int m = j / (C_ * C_);
        int c = j % C_;
        Wout_b[j] = __float2bfloat16(gamma[m * C_ + c] * Wout[j]);
    } else {
        int j = i - S1_ - S2_ - S3_;
        if (j < FUSEN_) {
            int m = j / 72, r = j % 72;
            bfo[j] = (r < OFFN_) ? boff[m * OFFN_ + r] : baw[m * AWN_ + r - OFFN_];
        } else if (j < FUSEN_ + C_) {
            int c = j - FUSEN_;
            float s = 0.f;
            #pragma unroll
            for (int m = 0; m < M_; m++) s += gamma[m * C_ + c] * bout[m * C_ + c];
            bout_t[c] = s;
        }
    }
}
#define PACK_TOTAL_ (S1_ + S2_ + S3_ + FUSEN_ + C_)

// ---------------- warp-per-row LayerNorm (5 sources fused) -------------------
__global__ void ln_kernel(const float* __restrict__ query,
                          const float* __restrict__ feat,
                          const float* __restrict__ feato,
                          const float* __restrict__ qn_g, const float* __restrict__ qn_b,
                          const float* __restrict__ fn_g, const float* __restrict__ fn_b,
                          __nv_bfloat16* __restrict__ qn,
                          __nv_bfloat16* __restrict__ fnAll)
{
    const int grow = blockIdx.x * 8 + (threadIdx.x >> 5);
    const int l = threadIdx.x & 31;
    const int src = grow / ROWS_;
    const int row = grow - src * ROWS_;

    const float* xbase = (src == 0) ? query : (src == 1 ? feat
                         : feato + (size_t)(src - 2) * ROWS_ * C_);
    const float* g = (src == 0) ? qn_g : fn_g + (src - 1) * C_;
    const float* b = (src == 0) ? qn_b : fn_b + (src - 1) * C_;
    __nv_bfloat16* y = (src == 0) ? qn + (size_t)row * C_
                                  : fnAll + ((size_t)(src - 1) * ROWS_ + row) * C_;
    const float4* xr = (const float4*)(xbase + (size_t)row * C_);

    float4 v[3];
    float sum = 0.f, sumsq = 0.f;
    #pragma unroll
    for (int k = 0; k < 3; k++) {
        v[k] = xr[l + 32 * k];
        sum   += v[k].x + v[k].y + v[k].z + v[k].w;
        sumsq += v[k].x * v[k].x + v[k].y * v[k].y + v[k].z * v[k].z + v[k].w * v[k].w;
    }
    #pragma unroll
    for (int o = 16; o; o >>= 1) {
        sum   += __shfl_xor_sync(0xffffffffu, sum, o);
        sumsq += __shfl_xor_sync(0xffffffffu, sumsq, o);
    }
    const float mean = sum * (1.f / C_);
    const float var  = sumsq * (1.f / C_) - mean * mean;
    const float inv  = rsqrtf(var + 1e-6f);

    const float4* g4 = (const float4*)g;
    const float4* b4 = (const float4*)b;
    #pragma unroll
    for (int k = 0; k < 3; k++) {
        float4 gg = g4[l + 32 * k];
        float4 bb = b4[l + 32 * k];
        __nv_bfloat16 o0 = __float2bfloat16((v[k].x - mean) * inv * gg.x + bb.x);
        __nv_bfloat16 o1 = __float2bfloat16((v[k].y - mean) * inv * gg.y + bb.y);
        __nv_bfloat16 o2 = __float2bfloat16((v[k].z - mean) * inv * gg.z + bb.z);
        __nv_bfloat16 o3 = __float2bfloat16((v[k].w - mean) * inv * gg.w + bb.w);
        uint2 pk;
        pk.x = ((uint32_t)__bfloat16_as_ushort(o1) << 16) | __bfloat16_as_ushort(o0);
        pk.y = ((uint32_t)__bfloat16_as_ushort(o3) << 16) | __bfloat16_as_ushort(o2);
        *(uint2*)&y[(l + 32 * k) * 4] = pk;
    }
}

// ---------------- 64-wide GEMM (offaw only, N=288, fp32 out) -----------------
#define AS_STRIDE 40
#define BS_STRIDE 72
__global__ __launch_bounds__(256) void gemm64(const __nv_bfloat16* __restrict__ A,
                                              const __nv_bfloat16* __restrict__ W,
                                              const float* __restrict__ bias,
                                              float* __restrict__ Cm, int N)
{
    __shared__ alignas(16) __nv_bfloat16 As[2][128][AS_STRIDE];
    __shared__ alignas(16) __nv_bfloat16 Bs[2][32][BS_STRIDE];
    const int tid = threadIdx.x;
    const int w = tid >> 5, l = tid & 31;
    const int warpM = (w & 3) << 5;
    const int warpN = (w >> 2) << 5;
    const int row0 = blockIdx.y * 128;
    const int col0 = blockIdx.x * 64;

    float acc[2][4][4];
    #pragma unroll
    for (int mi = 0; mi < 2; mi++)
        #pragma unroll
        for (int nj = 0; nj < 4; nj++)
            #pragma unroll
            for (int q = 0; q < 4; q++) acc[mi][nj][q] = 0.f;

    const int br = tid >> 3, bch = tid & 7;
    const int KIT = C_ / 32;

    for (int it = 0; it <= KIT; it++) {
        if (it < KIT) {
            const int st = it & 1;
            const int k0 = it * 32;
            #pragma unroll
            for (int i = 0; i < 2; i++) {
                int q = tid * 2 + i;
                int r = q >> 2, kc = q & 3;
                uint32_t d = (uint32_t)__cvta_generic_to_shared(&As[st][r][kc * 8]);
                const __nv_bfloat16* s = A + (size_t)(row0 + r) * C_ + k0 + kc * 8;
                asm volatile("cp.async.cg.shared.global [%0], [%1], 16;\n" :: "r"(d), "l"(s));
            }
            {
                int c = bch * 8;
                uint32_t d = (uint32_t)__cvta_generic_to_shared(&Bs[st][br][c]);
                const __nv_bfloat16* s = W + (size_t)(k0 + br) * N + col0 + c;
                int sb = (col0 + c < N) ? 16 : 0;
                if (sb == 0) s = W;
                asm volatile("cp.async.cg.shared.global [%0], [%1], 16, %2;\n"
                             :: "r"(d), "l"(s), "r"(sb));
            }
            asm volatile("cp.async.commit_group;\n");
        }
        if (it == 0) continue;
        if (it < KIT) asm volatile("cp.async.wait_group 1;\n");
        else          asm volatile("cp.async.wait_group 0;\n");
        __syncthreads();

        const int st = (it - 1) & 1;
        #pragma unroll
        for (int s = 0; s < 2; s++) {
            const int k16 = s * 16;
            uint32_t a[2][4], bfr[2][4];
            #pragma unroll
            for (int mi = 0; mi < 2; mi++) {
                uint32_t addr = (uint32_t)__cvta_generic_to_shared(
                    &As[st][warpM + mi * 16 + (l & 15)][k16 + (l >> 4) * 8]);
                asm volatile("ldmatrix.sync.aligned.m8n8.x4.shared.b16 {%0,%1,%2,%3}, [%4];\n"
                    : "=r"(a[mi][0]), "=r"(a[mi][1]), "=r"(a[mi][2]), "=r"(a[mi][3]) : "r"(addr));
            }
            #pragma unroll
            for (int np = 0; np < 2; np++) {
                uint32_t addr = (uint32_t)__cvta_generic_to_shared(
                    &Bs[st][k16 + (l & 15)][warpN + np * 16 + (l >> 4) * 8]);
                asm volatile("ldmatrix.sync.aligned.m8n8.x4.trans.shared.b16 {%0,%1,%2,%3}, [%4];\n"
                    : "=r"(bfr[np][0]), "=r"(bfr[np][1]), "=r"(bfr[np][2]), "=r"(bfr[np][3]) : "r"(addr));
            }
            #pragma unroll
            for (int mi = 0; mi < 2; mi++)
                #pragma unroll
                for (int nj = 0; nj < 4; nj++) {
                    uint32_t b0 = bfr[nj >> 1][(nj & 1) * 2];
                    uint32_t b1 = bfr[nj >> 1][(nj & 1) * 2 + 1];
                    asm volatile(
                        "mma.sync.aligned.m16n8k16.row.col.f32.bf16.bf16.f32 "
                        "{%0,%1,%2,%3}, {%4,%5,%6,%7}, {%8,%9}, {%0,%1,%2,%3};\n"
                        : "+f"(acc[mi][nj][0]), "+f"(acc[mi][nj][1]),
                          "+f"(acc[mi][nj][2]), "+f"(acc[mi][nj][3])
                        : "r"(a[mi][0]), "r"(a[mi][1]), "r"(a[mi][2]), "r"(a[mi][3]),
                          "r"(b0), "r"(b1));
                }
        }
        __syncthreads();
    }

    #pragma unroll
    for (int mi = 0; mi < 2; mi++) {
        const int r = row0 + warpM + mi * 16 + (l >> 2);
        #pragma unroll
        for (int nj = 0; nj < 4; nj++) {
            const int c = col0 + warpN + nj * 8 + ((l & 3) << 1);
            if (c >= N) continue;
            const float b0 = bias[c], b1 = bias[c + 1];
            *(float2*)&Cm[(size_t)r * N + c]       = make_float2(acc[mi][nj][0] + b0, acc[mi][nj][1] + b1);
            *(float2*)&Cm[(size_t)(r + 8) * N + c] = make_float2(acc[mi][nj][2] + b0, acc[mi][nj][3] + b1);
        }
    }
}

// ---------------- 128x128 GEMM, N=384 exact, 2-stage static smem -------------
#define BS2_STRIDE 136
template<int KA, int MODE>
__global__ __launch_bounds__(256) void gemm128(const __nv_bfloat16* __restrict__ A,
                                               const __nv_bfloat16* __restrict__ W,
                                               const float* __restrict__ bias,
                                               void* __restrict__ Cout,
                                               const float* __restrict__ residual)
{
    __shared__ alignas(16) __nv_bfloat16 As[2][128][AS_STRIDE];
    __shared__ alignas(16) __nv_bfloat16 Bs[2][32][BS2_STRIDE];
    const int N = C_;
    const int tid = threadIdx.x;
    const int w = tid >> 5, l = tid & 31;
    const int warpM = (w & 1) << 6;     // 0,64
    const int warpN = (w >> 1) << 5;    // 0,32,64,96
    const int row0 = blockIdx.y * 128;
    const int col0 = blockIdx.x * 128;

    if (MODE == 1) {
        const int zb = blockIdx.z;
        A    += (size_t)zb * ROWS_ * KA;
        W    += (size_t)zb * KA * N;
        bias += (size_t)zb * N;
    }

    float acc[4][4][4];
    #pragma unroll
    for (int mi = 0; mi < 4; mi++)
        #pragma unroll
        for (int nj = 0; nj < 4; nj++)
            #pragma unroll
            for (int q = 0; q < 4; q++) acc[mi][nj][q] = 0.f;

    const int KIT = KA / 32;

    for (int it = 0; it <= KIT; it++) {
        if (it < KIT) {
            const int st = it & 1;
            const int k0 = it * 32;
            #pragma unroll
            for (int i = 0; i < 2; i++) {
                int q = tid * 2 + i;
                int r = q >> 2, kc = q & 3;
                uint32_t d = (uint32_t)__cvta_generic_to_shared(&As[st][r][kc * 8]);
                const __nv_bfloat16* s = A + (size_t)(row0 + r) * KA + k0 + kc * 8;
                asm volatile("cp.async.cg.shared.global [%0], [%1], 16;\n" :: "r"(d), "l"(s));
            }
            #pragma unroll
            for (int i = 0; i < 2; i++) {
                int r = (tid >> 4) + i * 16;
                int c = (tid & 15) * 8;
                uint32_t d = (uint32_t)__cvta_generic_to_shared(&Bs[st][r][c]);
                const __nv_bfloat16* s = W + (size_t)(k0 + r) * N + col0 + c;
                asm volatile("cp.async.cg.shared.global [%0], [%1], 16;\n" :: "r"(d), "l"(s));
            }
            asm volatile("cp.async.commit_group;\n");
        }
        if (it == 0) continue;
        if (it < KIT) asm volatile("cp.async.wait_group 1;\n");
        else          asm volatile("cp.async.wait_group 0;\n");
        __syncthreads();

        const int st = (it - 1) & 1;
        #pragma unroll
        for (int s = 0; s < 2; s++) {
            const int k16 = s * 16;
            uint32_t a[4][4], bfr[2][4];
            #pragma unroll
            for (int mi = 0; mi < 4; mi++) {
                uint32_t addr = (uint32_t)__cvta_generic_to_shared(
                    &As[st][warpM + mi * 16 + (l & 15)][k16 + (l >> 4) * 8]);
                asm volatile("ldmatrix.sync.aligned.m8n8.x4.shared.b16 {%0,%1,%2,%3}, [%4];\n"
                    : "=r"(a[mi][0]), "=r"(a[mi][1]), "=r"(a[mi][2]), "=r"(a[mi][3]) : "r"(addr));
            }
            #pragma unroll
            for (int np = 0; np < 2; np++) {
                uint32_t addr = (uint32_t)__cvta_generic_to_shared(
                    &Bs[st][k16 + (l & 15)][warpN + np * 16 + (l >> 4) * 8]);
                asm volatile("ldmatrix.sync.aligned.m8n8.x4.trans.shared.b16 {%0,%1,%2,%3}, [%4];\n"
                    : "=r"(bfr[np][0]), "=r"(bfr[np][1]), "=r"(bfr[np][2]), "=r"(bfr[np][3]) : "r"(addr));
            }
            #pragma unroll
            for (int mi = 0; mi < 4; mi++)
                #pragma unroll
                for (int nj = 0; nj < 4; nj++) {
                    uint32_t b0 = bfr[nj >> 1][(nj & 1) * 2];
                    uint32_t b1 = bfr[nj >> 1][(nj & 1) * 2 + 1];
                    asm volatile(
                        "mma.sync.aligned.m16n8k16.row.col.f32.bf16.bf16.f32 "
                        "{%0,%1,%2,%3}, {%4,%5,%6,%7}, {%8,%9}, {%0,%1,%2,%3};\n"
                        : "+f"(acc[mi][nj][0]), "+f"(acc[mi][nj][1]),
                          "+f"(acc[mi][nj][2]), "+f"(acc[mi][nj][3])
                        : "r"(a[mi][0]), "r"(a[mi][1]), "r"(a[mi][2]), "r"(a[mi][3]),
                          "r"(b0), "r"(b1));
                }
        }
        __syncthreads();
    }

    #pragma unroll
    for (int mi = 0; mi < 4; mi++) {
        const int r = row0 + warpM + mi * 16 + (l >> 2);
        #pragma unroll
        for (int nj = 0; nj < 4; nj++) {
            const int c = col0 + warpN + nj * 8 + ((l & 3) << 1);
            const float b0 = bias[c], b1 = bias[c + 1];
            float v0 = acc[mi][nj][0] + b0;
            float v1 = acc[mi][nj][1] + b1;
            float v2 = acc[mi][nj][2] + b0;
            float v3 = acc[mi][nj][3] + b1;
            const size_t o0 = (size_t)r * N + c;
            const size_t o1 = (size_t)(r + 8) * N + c;
            if (MODE == 1) {
                __nv_bfloat16* Cm = (__nv_bfloat16*)Cout + (size_t)blockIdx.z * ROWS_ * N;
                *(__nv_bfloat162*)&Cm[o0] = __nv_bfloat162(__float2bfloat16(v0), __float2bfloat16(v1));
                *(__nv_bfloat162*)&Cm[o1] = __nv_bfloat162(__float2bfloat16(v2), __float2bfloat16(v3));
            } else {
                float* Cm = (float*)Cout;
                float2 r0 = *(const float2*)&residual[o0];
                float2 r1 = *(const float2*)&residual[o1];
                *(float2*)&Cm[o0] = make_float2(r0.x + v0, r0.y + v1);
                *(float2*)&Cm[o1] = make_float2(r1.x + v2, r1.y + v3);
            }
        }
    }
}

// ---------------- batched sampler: 8 ch/thread, pure int32 indexing ----------
__global__ void sample_kernel(const __nv_bfloat16* __restrict__ valueAll,
                              const float* __restrict__ ref,
                              const float* __restrict__ offaw,
                              __nv_bfloat16* __restrict__ attn,
                              const int* __restrict__ shapes_raw,
                              const int* __restrict__ lstart_raw)
{
    const int t   = threadIdx.x;
    const int idx = blockIdx.x * 32 + (t >> 3);   // over M*B*Lq*H
    const int l8  = t & 7;
    const int m   = idx / (ROWS_ * H_);
    const int rem = idx % (ROWS_ * H_);
    const int h   = rem % H_;
    const int bq  = rem / H_;
    const int b   = bq / LQ_;

    const int gh = shapes_raw[0];
    const int w1 = shapes_raw[1];
    const int gw = (w1 != 0) ? w1 : shapes_raw[2];
    const int st = lstart_raw[0];

    const float* fo = offaw + bq * FUSEN_ + m * 72;   // int32 index (max 2.36M)

    float a4[P_];
    float amax = -1e30f;
    #pragma unroll
    for (int p = 0; p < P_; p++) {
        a4[p] = fo[OFFN_ + h * P_ + p];
        amax = fmaxf(amax, a4[p]);
    }
    float asum = 0.f;
    #pragma unroll
    for (int p = 0; p < P_; p++) { a4[p] = __expf(a4[p] - amax); asum += a4[p]; }
    const float ainv = 1.f / asum;

    const float rx = ref[bq * 2 + 0];
    const float ry = ref[bq * 2 + 1];
    const float inv_w = 1.f / (float)gw;
    const float inv_h = 1.f / (float)gh;

    // int32 base: uint4 view index = vbase + pos*(H_*8); max ~600K, fits easily
    const uint4* vb = (const uint4*)(valueAll) + m * (ROWS_ * C_ / 8)
                      + ((b * LQ_ + st) * H_ + h) * 8 + l8;

    float out[8] = {};
    #pragma unroll
    for (int p = 0; p < P_; p++) {
        const float ox = fo[h * (P_ * 2) + p * 2 + 0];
        const float oy = fo[h * (P_ * 2) + p * 2 + 1];
        const float x = (rx + ox * inv_w) * (float)gw - 0.5f;
        const float y = (ry + oy * inv_h) * (float)gh - 0.5f;
        const float xf = floorf(x);
        const float yf = floorf(y);
        const int x0 = (int)xf;
        const int y0 = (int)yf;
        const float wx = x - xf;
        const float wy = y - yf;
        const float aws = a4[p] * ainv;

        #pragma unroll
        for (int cy = 0; cy < 2; cy++) {
            const int yi = y0 + cy;
            if (yi < 0 || yi >= gh) continue;
            const float wyc = (cy ? wy : (1.f - wy)) * aws;
            #pragma unroll
            for (int cx = 0; cx < 2; cx++) {
                const int xi = x0 + cx;
                if (xi < 0 || xi >= gw) continue;
                const float wgt = wyc * (cx ? wx : (1.f - wx));
                const int pos = yi * gw + xi;            // grid-local position
                uint4 v = vb[pos * (H_ * 8)];            // single 32-bit IMAD
                const uint32_t* vw = (const uint32_t*)&v;
                #pragma unroll
                for (int k = 0; k < 4; k++) {
                    __nv_bfloat162 pr = *(const __nv_bfloat162*)&vw[k];
                    out[2 * k]     = fmaf(wgt, __bfloat162float(pr.x), out[2 * k]);
                    out[2 * k + 1] = fmaf(wgt, __bfloat162float(pr.y), out[2 * k + 1]);
                }
            }
        }
    }
    uint4 pk;
    uint32_t* pw = (uint32_t*)&pk;
    #pragma unroll
    for (int k = 0; k < 4; k++) {
        __nv_bfloat162 pr(__float2bfloat16(out[2 * k]), __float2bfloat16(out[2 * k + 1]));
        pw[k] = *(const uint32_t*)&pr;
    }
    ((uint4*)attn)[bq * (KOUT_ / 8) + m * (C_ / 8) + h * (DH_ / 8) + l8] = pk;
}

// ---------------- driver -----------------------------------------------------
extern "C" void kernel_launch(void* const* d_in, const int* in_sizes, int n_in,
                              void* d_out, int out_size)
{
    const float* query = (const float*)d_in[0];
    const float* ref   = (const float*)d_in[1];
    const float* feat  = (const float*)d_in[2];
    const float* feato = (const float*)d_in[3];
    const float* qn_g  = (const float*)d_in[4];
    const float* qn_b  = (const float*)d_in[5];
    const float* fn_g  = (const float*)d_in[6];
    const float* fn_b  = (const float*)d_in[7];
    const float* Wv    = (const float*)d_in[8];
    const float* bv    = (const float*)d_in[9];
    const float* Woff  = (const float*)d_in[10];
    const float* boff  = (const float*)d_in[11];
    const float* Waw   = (const float*)d_in[12];
    const float* baw   = (const float*)d_in[13];
    const float* Wout  = (const float*)d_in[14];
    const float* bout  = (const float*)d_in[15];
    const float* gamma = (const float*)d_in[16];
    const int* shapes  = (const int*)d_in[17];
    const int* lstart  = (const int*)d_in[18];
    float* out = (float*)d_out;

    __nv_bfloat16 *qn, *fn, *value, *attn, *Wv_b, *Wfo_b, *Wout_b;
    float *offaw, *bfo, *bout_t;
    cudaGetSymbolAddress((void**)&qn,     g_qn);
    cudaGetSymbolAddress((void**)&fn,     g_fn);
    cudaGetSymbolAddress((void**)&value,  g_value);
    cudaGetSymbolAddress((void**)&offaw,  g_offaw);
    cudaGetSymbolAddress((void**)&attn,   g_attn);
    cudaGetSymbolAddress((void**)&Wv_b,   g_Wv_b);
    cudaGetSymbolAddress((void**)&Wfo_b,  g_Wfo_b);
    cudaGetSymbolAddress((void**)&bfo,    g_bfo);
    cudaGetSymbolAddress((void**)&Wout_b, g_Wout_b);
    cudaGetSymbolAddress((void**)&bout_t, g_bout);

    pack_all_kernel<<<(PACK_TOTAL_ + 255) / 256, 256>>>(
        Wv, Woff, Waw, Wout, gamma, boff, baw, bout,
        Wv_b, Wfo_b, Wout_b, bfo, bout_t);

    ln_kernel<<<5 * ROWS_ / 8, 256>>>(query, feat, feato, qn_g, qn_b, fn_g, fn_b, qn, fn);

    gemm64<<<dim3((FUSEN_ + 63) / 64, ROWS_ / 128), 256>>>(qn, Wfo_b, bfo, offaw, FUSEN_);

    gemm128<C_, 1><<<dim3(C_ / 128, ROWS_ / 128, M_), 256>>>(fn, Wv_b, bv, value, nullptr);

    sample_kernel<<<(M_ * ROWS_ * H_) / 32, 256>>>(value, ref, offaw, attn, shapes, lstart);

    gemm128<KOUT_, 2><<<dim3(C_ / 128, ROWS_ / 128), 256>>>(attn, Wout_b, bout_t, out, query);
}